// round 8
// baseline (speedup 1.0000x reference)
#include <cuda_runtime.h>
#include <math.h>
#include <float.h>

#define B 8
#define SEQ 12
#define NN 1000
#define E 16000
#define HID 128
#define HEADS 8
#define DH 16
#define M_ROWS (B*NN)          /* 8000 */

#define NBLK 125               /* <= 148 SMs: all blocks co-resident -> grid barrier safe */
#define AT_STRIDE 68
#define GEMM_SMEM (HID*HID*4 + HID*AT_STRIDE*4)   /* 64KB W + 34KB A^T */

// ---------------- static device scratch ----------------
__device__ float g_hin[(size_t)SEQ*B*NN*HID];
__device__ float g_y  [(size_t)M_ROWS*HID];
__device__ float g_hp [(size_t)M_ROWS*HID];
__device__ float g_k1 [(size_t)M_ROWS*HID];
__device__ float g_k2 [(size_t)M_ROWS*HID];
__device__ float g_k3 [(size_t)M_ROWS*HID];
__device__ float g_tmp[(size_t)M_ROWS*HID];
__device__ float g_el [(size_t)M_ROWS*HEADS];
__device__ float g_er [(size_t)M_ROWS*HEADS];
__device__ int   g_cnt[NN];
__device__ int   g_cur[NN];
__device__ int   g_off[NN+1];
__device__ int   g_eidx[E];

// ---------------- software grid barrier (all NBLK blocks resident) ----------------
__device__ unsigned          g_bar_cnt = 0;
__device__ volatile unsigned g_bar_gen = 0;

__device__ __forceinline__ void grid_barrier(){
    __syncthreads();
    if (threadIdx.x == 0){
        __threadfence();
        unsigned gen = g_bar_gen;
        unsigned t = atomicAdd(&g_bar_cnt, 1u);
        if (t == NBLK-1){
            atomicExch(&g_bar_cnt, 0u);
            __threadfence();
            g_bar_gen = gen + 1u;
        } else {
            while (g_bar_gen == gen) { }
        }
        __threadfence();
    }
    __syncthreads();
}

// ---------------- fused init: inproj + y=h[:,0] + CSR zero ----------------
__global__ void k_init(const float* __restrict__ inp, const float* __restrict__ w_in,
                       const float* __restrict__ b_in, float* __restrict__ hin,
                       float* __restrict__ y, int* cnt, int* cur){
    int row = blockIdx.x;
    int t = threadIdx.x;
    if (blockIdx.x < 8){
        int q = blockIdx.x*128 + t;
        if (q < NN){ cnt[q] = 0; cur[q] = 0; }
    }
    int b = row / (SEQ*NN);
    int s = (row / NN) % SEQ;
    int n = row % NN;
    float x0 = inp[(size_t)row*2 + 0];
    float x1 = inp[(size_t)row*2 + 1];
    float v = fmaf(x0, w_in[t], fmaf(x1, w_in[HID+t], b_in[t]));
    hin[(((size_t)s*B + b)*NN + n)*HID + t] = v;
    if (s == 0) y[((size_t)b*NN + n)*HID + t] = v;
}

// ---------------- CSR construction (deterministic) ----------------
__global__ void k_csr_count(const int* __restrict__ dst, int* cnt){
    int e = blockIdx.x*blockDim.x + threadIdx.x;
    if (e < E) atomicAdd(&cnt[dst[e]], 1);
}
__global__ void k_csr_scan(const int* __restrict__ cnt, int* off){
    __shared__ int s[1024];
    int t = threadIdx.x;
    s[t] = (t < NN) ? cnt[t] : 0;
    __syncthreads();
    #pragma unroll
    for (int o = 1; o < 1024; o <<= 1){
        int v = (t >= o) ? s[t-o] : 0;
        __syncthreads();
        s[t] += v;
        __syncthreads();
    }
    if (t == 0) off[0] = 0;
    if (t < NN) off[t+1] = s[t];
}
__global__ void k_csr_fill(const int* __restrict__ dst, const int* __restrict__ off,
                           int* cur, int* eidx){
    int e = blockIdx.x*blockDim.x + threadIdx.x;
    if (e < E){
        int d = dst[e];
        int p = atomicAdd(&cur[d], 1);
        eidx[off[d] + p] = e;
    }
}
__global__ void k_csr_sort(const int* __restrict__ off, int* eidx){
    if (threadIdx.x != 0) return;
    int n = blockIdx.x;
    int a = off[n], b = off[n+1];
    for (int i = a+1; i < b; i++){
        int v = eidx[i]; int j = i-1;
        while (j >= a && eidx[j] > v){ eidx[j+1] = eidx[j]; j--; }
        eidx[j+1] = v;
    }
}

// ================= persistent RK4 ODE kernel: one launch = 4 RK4 steps =========
// NBLK blocks x 512 threads. W_gat staged to smem ONCE. Each (gemm,gat) phase pair
// separated by grid barriers; all 16 gemm + 16 gat phases run in one launch.
__global__ void __launch_bounds__(512) k_ode(
    const float* __restrict__ w_gat,
    const float* __restrict__ a_l, const float* __restrict__ a_r,
    float* __restrict__ y, float* __restrict__ hp,
    float* __restrict__ k1, float* __restrict__ k2, float* __restrict__ k3,
    float* __restrict__ el, float* __restrict__ er,
    const int* __restrict__ off, const int* __restrict__ eidx,
    const int* __restrict__ src)
{
    extern __shared__ float smem[];
    float* sW  = smem;                 // [128][128] — resident全launch
    float* sAT = smem + HID*HID;       // [128][AT_STRIDE]

    const unsigned FULL = 0xffffffffu;
    int tid = threadIdx.x;
    int tx = tid & 31, ty = tid >> 5;  // lane / warp(0..15)
    int row0 = blockIdx.x * 64;
    int col0 = tx * 4;
    const float dtc = 0.25f / 6.0f;

    // ---- stage W once per launch ----
    {
        const float4* W4 = (const float4*)w_gat;
        float4* sW4 = (float4*)sW;
        for (int i = tid; i < HID*32; i += 512) sW4[i] = W4[i];
    }

    for (int step = 0; step < 4; step++){
        for (int st = 0; st < 4; st++){
            const float* A1 = (st==0) ? (const float*)0 : (st==1 ? k1 : (st==2 ? k2 : k3));
            float c1 = (st==3) ? 0.25f : 0.125f;

            // ======== GEMM phase: hp[row0..row0+64) = (y + c1*A1) @ W ========
            {
                const float4* A04 = (const float4*)y;
                const float4* A14 = (const float4*)A1;
                for (int i = tid; i < 64*32; i += 512){
                    int r = i >> 5, c4 = i & 31;
                    float4 v = A04[(size_t)(row0+r)*32 + c4];
                    if (A1){
                        float4 u = A14[(size_t)(row0+r)*32 + c4];
                        v.x = fmaf(c1,u.x,v.x); v.y = fmaf(c1,u.y,v.y);
                        v.z = fmaf(c1,u.z,v.z); v.w = fmaf(c1,u.w,v.w);
                    }
                    int k0 = c4*4;
                    sAT[(k0+0)*AT_STRIDE + r] = v.x;
                    sAT[(k0+1)*AT_STRIDE + r] = v.y;
                    sAT[(k0+2)*AT_STRIDE + r] = v.z;
                    sAT[(k0+3)*AT_STRIDE + r] = v.w;
                }
            }
            __syncthreads();
            float acc[4][4];
            #pragma unroll
            for (int i=0;i<4;i++)
                #pragma unroll
                for (int j=0;j<4;j++) acc[i][j] = 0.f;
            {
                const float4* sW4 = (const float4*)sW;
                #pragma unroll 4
                for (int k = 0; k < HID; k++){
                    float4 w = sW4[k*32 + tx];
                    float4 a = *reinterpret_cast<const float4*>(sAT + k*AT_STRIDE + ty*4);
                    float av[4] = {a.x,a.y,a.z,a.w};
                    #pragma unroll
                    for (int i=0;i<4;i++){
                        acc[i][0] = fmaf(av[i], w.x, acc[i][0]);
                        acc[i][1] = fmaf(av[i], w.y, acc[i][1]);
                        acc[i][2] = fmaf(av[i], w.z, acc[i][2]);
                        acc[i][3] = fmaf(av[i], w.w, acc[i][3]);
                    }
                }
            }
            #pragma unroll
            for (int i=0;i<4;i++){
                int r = row0 + ty*4 + i;
                float4 o;
                o.x = acc[i][0]; o.y = acc[i][1]; o.z = acc[i][2]; o.w = acc[i][3];
                *reinterpret_cast<float4*>(hp + (size_t)r*HID + col0) = o;
            }
            // el/er epilogue (head = tx>>2)
            {
                int head  = tx >> 2;
                int dbase = (tx & 3) * 4;
                #pragma unroll
                for (int i=0;i<4;i++){
                    float pl = 0.f, pr = 0.f;
                    #pragma unroll
                    for (int j=0;j<4;j++){
                        pl = fmaf(acc[i][j], a_l[head*DH + dbase + j], pl);
                        pr = fmaf(acc[i][j], a_r[head*DH + dbase + j], pr);
                    }
                    pl += __shfl_xor_sync(FULL, pl, 1);
                    pl += __shfl_xor_sync(FULL, pl, 2);
                    pr += __shfl_xor_sync(FULL, pr, 1);
                    pr += __shfl_xor_sync(FULL, pr, 2);
                    if ((tx & 3) == 0){
                        int r = row0 + ty*4 + i;
                        el[(size_t)r*HEADS + head] = pl;
                        er[(size_t)r*HEADS + head] = pr;
                    }
                }
            }
            grid_barrier();

            // ======== GAT phase: warp gw handles bn = gw*4 .. gw*4+3 ========
            {
                float* kout = (st==0) ? k1 : (st==1) ? k2 : (st==2) ? k3 : y;
                int gw = blockIdx.x*16 + ty;
                int lane = tx;
                #pragma unroll 1
                for (int p = 0; p < 4; p++){
                    int bn = gw*4 + p;
                    int b = bn / NN, n = bn - b*NN;
                    const float* hb  = hp + (size_t)b*NN*HID;
                    const float* elb = el + (size_t)b*NN*HEADS;

                    float erv[8];
                    {
                        float4 e0v = *reinterpret_cast<const float4*>(er + (size_t)bn*HEADS);
                        float4 e1v = *reinterpret_cast<const float4*>(er + (size_t)bn*HEADS + 4);
                        erv[0]=e0v.x; erv[1]=e0v.y; erv[2]=e0v.z; erv[3]=e0v.w;
                        erv[4]=e1v.x; erv[5]=e1v.y; erv[6]=e1v.z; erv[7]=e1v.w;
                    }
                    int e0 = off[n], deg = off[n+1] - e0;

                    float acg[4] = {0.f,0.f,0.f,0.f};
                    float m[8], ssum[8];
                    #pragma unroll
                    for (int h=0;h<8;h++){ m[h] = -FLT_MAX; ssum[h] = 0.f; }

                    for (int base = 0; base < deg; base += 32){
                        int cnt2 = min(32, deg - base);
                        int sj = 0;
                        float lg[8];
                        if (lane < cnt2){
                            sj = src[eidx[e0 + base + lane]];
                            float4 v0 = *reinterpret_cast<const float4*>(elb + (size_t)sj*HEADS);
                            float4 v1 = *reinterpret_cast<const float4*>(elb + (size_t)sj*HEADS + 4);
                            float t0;
                            t0 = v0.x + erv[0]; lg[0] = (t0>=0.f)?t0:0.2f*t0;
                            t0 = v0.y + erv[1]; lg[1] = (t0>=0.f)?t0:0.2f*t0;
                            t0 = v0.z + erv[2]; lg[2] = (t0>=0.f)?t0:0.2f*t0;
                            t0 = v0.w + erv[3]; lg[3] = (t0>=0.f)?t0:0.2f*t0;
                            t0 = v1.x + erv[4]; lg[4] = (t0>=0.f)?t0:0.2f*t0;
                            t0 = v1.y + erv[5]; lg[5] = (t0>=0.f)?t0:0.2f*t0;
                            t0 = v1.z + erv[6]; lg[6] = (t0>=0.f)?t0:0.2f*t0;
                            t0 = v1.w + erv[7]; lg[7] = (t0>=0.f)?t0:0.2f*t0;
                        } else {
                            #pragma unroll
                            for (int h=0;h<8;h++) lg[h] = -FLT_MAX;
                        }
                        float nm[8];
                        #pragma unroll
                        for (int h=0;h<8;h++) nm[h] = lg[h];
                        #pragma unroll
                        for (int o = 16; o > 0; o >>= 1){
                            #pragma unroll
                            for (int h=0;h<8;h++)
                                nm[h] = fmaxf(nm[h], __shfl_xor_sync(FULL, nm[h], o));
                        }
                        float w[8], sc[8];
                        #pragma unroll
                        for (int h=0;h<8;h++){
                            float newm = fmaxf(m[h], nm[h]);
                            sc[h] = (m[h] == -FLT_MAX) ? 0.f : __expf(m[h] - newm);
                            m[h]  = newm;
                            w[h]  = __expf(lg[h] - newm);
                        }
                        if (base > 0){
                            #pragma unroll
                            for (int g=0;g<4;g++){
                                float s01 = (lane < 16) ? sc[2*g] : sc[2*g+1];
                                acg[g] *= s01;
                            }
                            #pragma unroll
                            for (int h=0;h<8;h++) ssum[h] *= sc[h];
                        }
                        float cs[8];
                        #pragma unroll
                        for (int h=0;h<8;h++) cs[h] = w[h];
                        #pragma unroll
                        for (int o = 16; o > 0; o >>= 1){
                            #pragma unroll
                            for (int h=0;h<8;h++)
                                cs[h] += __shfl_xor_sync(FULL, cs[h], o);
                        }
                        #pragma unroll
                        for (int h=0;h<8;h++) ssum[h] += cs[h];
                        for (int j = 0; j < cnt2; j++){
                            int s = __shfl_sync(FULL, sj, j);
                            const float* hr = hb + (size_t)s*HID;
                            #pragma unroll
                            for (int g=0;g<4;g++){
                                float wa = __shfl_sync(FULL, w[2*g],   j);
                                float wb = __shfl_sync(FULL, w[2*g+1], j);
                                float ww = (lane < 16) ? wa : wb;
                                acg[g] = fmaf(ww, hr[lane + 32*g], acg[g]);
                            }
                        }
                    }
                    #pragma unroll
                    for (int g=0;g<4;g++){
                        float s = ((lane < 16) ? ssum[2*g] : ssum[2*g+1]) + 1e-16f;
                        float kv = acg[g] / s;
                        size_t o = (size_t)bn*HID + lane + 32*g;
                        if (st == 3){
                            kout[o] = y[o] + dtc*(k1[o] + 2.f*k2[o] + 2.f*k3[o] + kv);
                        } else {
                            kout[o] = kv;
                        }
                    }
                }
            }
            grid_barrier();
        }
    }
}

// ---------------- standalone GEMM (tanh/LN + final head) ----------------
__global__ void __launch_bounds__(512) k_gemm(
    const float* __restrict__ A0,
    const float* __restrict__ W0,
    const float* __restrict__ A2, const float* __restrict__ W1,
    const float* __restrict__ b0, const float* __restrict__ b1,
    float* __restrict__ C, int act, int doLN)
{
    extern __shared__ float smem[];
    float* sW  = smem;
    float* sAT = smem + HID*HID;

    int row0 = blockIdx.x * 64;
    int tid = threadIdx.x;
    int tx = tid & 31, ty = tid >> 5;
    int col0 = tx * 4;

    float acc[4][4];
    #pragma unroll
    for (int i=0;i<4;i++)
        #pragma unroll
        for (int j=0;j<4;j++) acc[i][j] = 0.f;

    {
        const float4* W4 = (const float4*)W0;
        float4* sW4 = (float4*)sW;
        for (int i = tid; i < HID*32; i += 512) sW4[i] = W4[i];
        const float4* A04 = (const float4*)A0;
        for (int i = tid; i < 64*32; i += 512){
            int r = i >> 5, c4 = i & 31;
            float4 v = A04[(size_t)(row0+r)*32 + c4];
            int k0 = c4*4;
            sAT[(k0+0)*AT_STRIDE + r] = v.x;
            sAT[(k0+1)*AT_STRIDE + r] = v.y;
            sAT[(k0+2)*AT_STRIDE + r] = v.z;
            sAT[(k0+3)*AT_STRIDE + r] = v.w;
        }
    }
    __syncthreads();
    {
        const float4* sW4 = (const float4*)sW;
        #pragma unroll 4
        for (int k = 0; k < HID; k++){
            float4 w = sW4[k*32 + tx];
            float4 a = *reinterpret_cast<const float4*>(sAT + k*AT_STRIDE + ty*4);
            float av[4] = {a.x,a.y,a.z,a.w};
            #pragma unroll
            for (int i=0;i<4;i++){
                acc[i][0] = fmaf(av[i], w.x, acc[i][0]);
                acc[i][1] = fmaf(av[i], w.y, acc[i][1]);
                acc[i][2] = fmaf(av[i], w.z, acc[i][2]);
                acc[i][3] = fmaf(av[i], w.w, acc[i][3]);
            }
        }
    }
    if (A2){
        __syncthreads();
        {
            const float4* W4 = (const float4*)W1;
            float4* sW4 = (float4*)sW;
            for (int i = tid; i < HID*32; i += 512) sW4[i] = W4[i];
            const float4* A24 = (const float4*)A2;
            for (int i = tid; i < 64*32; i += 512){
                int r = i >> 5, c4 = i & 31;
                float4 v = A24[(size_t)(row0+r)*32 + c4];
                int k0 = c4*4;
                sAT[(k0+0)*AT_STRIDE + r] = v.x;
                sAT[(k0+1)*AT_STRIDE + r] = v.y;
                sAT[(k0+2)*AT_STRIDE + r] = v.z;
                sAT[(k0+3)*AT_STRIDE + r] = v.w;
            }
        }
        __syncthreads();
        const float4* sW4 = (const float4*)sW;
        #pragma unroll 4
        for (int k = 0; k < HID; k++){
            float4 w = sW4[k*32 + tx];
            float4 a = *reinterpret_cast<const float4*>(sAT + k*AT_STRIDE + ty*4);
            float av[4] = {a.x,a.y,a.z,a.w};
            #pragma unroll
            for (int i=0;i<4;i++){
                acc[i][0] = fmaf(av[i], w.x, acc[i][0]);
                acc[i][1] = fmaf(av[i], w.y, acc[i][1]);
                acc[i][2] = fmaf(av[i], w.z, acc[i][2]);
                acc[i][3] = fmaf(av[i], w.w, acc[i][3]);
            }
        }
    }
    float bias[4] = {0.f,0.f,0.f,0.f};
    if (b0){
        #pragma unroll
        for (int j=0;j<4;j++) bias[j] += b0[col0+j];
    }
    if (b1){
        #pragma unroll
        for (int j=0;j<4;j++) bias[j] += b1[col0+j];
    }
    #pragma unroll
    for (int i=0;i<4;i++){
        #pragma unroll
        for (int j=0;j<4;j++){
            acc[i][j] += bias[j];
            if (act) acc[i][j] = tanhf(acc[i][j]);
        }
    }
    if (doLN){
        #pragma unroll
        for (int i=0;i<4;i++){
            float s = acc[i][0]+acc[i][1]+acc[i][2]+acc[i][3];
            #pragma unroll
            for (int o = 16; o > 0; o >>= 1) s += __shfl_xor_sync(0xffffffffu, s, o);
            float mean = s * (1.f/HID);
            float d0 = acc[i][0]-mean, d1 = acc[i][1]-mean,
                  d2 = acc[i][2]-mean, d3 = acc[i][3]-mean;
            float q = d0*d0 + d1*d1 + d2*d2 + d3*d3;
            #pragma unroll
            for (int o = 16; o > 0; o >>= 1) q += __shfl_xor_sync(0xffffffffu, q, o);
            float inv = 1.0f / sqrtf(q * (1.f/HID) + 1e-5f);
            acc[i][0] = d0*inv; acc[i][1] = d1*inv;
            acc[i][2] = d2*inv; acc[i][3] = d3*inv;
        }
    }
    #pragma unroll
    for (int i=0;i<4;i++){
        int r = row0 + ty*4 + i;
        float4 o;
        o.x = acc[i][0]; o.y = acc[i][1]; o.z = acc[i][2]; o.w = acc[i][3];
        *reinterpret_cast<float4*>(C + (size_t)r*HID + col0) = o;
    }
}

// ---------------- LayerNorm (idx==0 only) ----------------
__global__ void __launch_bounds__(128) k_ln(const float* __restrict__ s, float* __restrict__ d){
    int row = blockIdx.x;
    int t = threadIdx.x;
    __shared__ float sh[4];
    float v = s[(size_t)row*HID + t];

    float a = v;
    #pragma unroll
    for (int o = 16; o > 0; o >>= 1) a += __shfl_xor_sync(0xffffffffu, a, o);
    if ((t & 31) == 0) sh[t >> 5] = a;
    __syncthreads();
    float mean = (sh[0]+sh[1]+sh[2]+sh[3]) * (1.f/HID);

    float dv = v - mean;
    float q = dv*dv;
    __syncthreads();
    #pragma unroll
    for (int o = 16; o > 0; o >>= 1) q += __shfl_xor_sync(0xffffffffu, q, o);
    if ((t & 31) == 0) sh[t >> 5] = q;
    __syncthreads();
    float var = (sh[0]+sh[1]+sh[2]+sh[3]) * (1.f/HID);

    d[(size_t)row*HID + t] = dv / sqrtf(var + 1e-5f);
}

// ---------------- launch ----------------
extern "C" void kernel_launch(void* const* d_in, const int* in_sizes, int n_in,
                              void* d_out, int out_size)
{
    const float* inputs = (const float*)d_in[0];
    const int*   src    = (const int*)  d_in[1];
    const int*   dst    = (const int*)  d_in[2];
    const float* w_in   = (const float*)d_in[3];
    const float* b_in   = (const float*)d_in[4];
    const float* w_gat  = (const float*)d_in[5];
    const float* a_l    = (const float*)d_in[6];
    const float* a_r    = (const float*)d_in[7];
    const float* w_W    = (const float*)d_in[8];
    const float* b_W    = (const float*)d_in[9];
    const float* w_U    = (const float*)d_in[10];
    const float* b_U    = (const float*)d_in[11];
    const float* w_o1   = (const float*)d_in[12];
    const float* b_o1   = (const float*)d_in[13];
    const float* w_o2   = (const float*)d_in[14];
    const float* b_o2   = (const float*)d_in[15];
    float* out = (float*)d_out;

    float *hin, *y, *hp, *k1, *k2, *k3, *tmp, *el, *er;
    int *cnt, *cur, *off, *eidx;
    cudaGetSymbolAddress((void**)&hin, g_hin);
    cudaGetSymbolAddress((void**)&y,   g_y);
    cudaGetSymbolAddress((void**)&hp,  g_hp);
    cudaGetSymbolAddress((void**)&k1,  g_k1);
    cudaGetSymbolAddress((void**)&k2,  g_k2);
    cudaGetSymbolAddress((void**)&k3,  g_k3);
    cudaGetSymbolAddress((void**)&tmp, g_tmp);
    cudaGetSymbolAddress((void**)&el,  g_el);
    cudaGetSymbolAddress((void**)&er,  g_er);
    cudaGetSymbolAddress((void**)&cnt, g_cnt);
    cudaGetSymbolAddress((void**)&cur, g_cur);
    cudaGetSymbolAddress((void**)&off, g_off);
    cudaGetSymbolAddress((void**)&eidx,g_eidx);

    const float* F0 = (const float*)0;

    static bool attr_set = false;
    if (!attr_set){
        cudaFuncSetAttribute(k_ode,  cudaFuncAttributeMaxDynamicSharedMemorySize, GEMM_SMEM);
        cudaFuncSetAttribute(k_gemm, cudaFuncAttributeMaxDynamicSharedMemorySize, GEMM_SMEM);
        attr_set = true;
    }

    // prelude
    k_init     <<<B*SEQ*NN, HID>>>(inputs, w_in, b_in, hin, y, cnt, cur);
    k_csr_count<<<(E+255)/256, 256>>>(dst, cnt);
    k_csr_scan <<<1, 1024>>>(cnt, off);
    k_csr_fill <<<(E+255)/256, 256>>>(dst, off, cur, eidx);
    k_csr_sort <<<NN, 32>>>(off, eidx);

    for (int idx = 0; idx < SEQ; idx++){
        // 4 RK4 steps (16 gemm + 16 gat phases) in ONE persistent launch
        k_ode<<<NBLK, 512, GEMM_SMEM>>>(w_gat, a_l, a_r, y, hp, k1, k2, k3,
                                        el, er, off, eidx, src);
        if (idx > 0){
            const float* hidx = hin + (size_t)idx * M_ROWS * HID;
            // y = LN(tanh(y@w_W + h[idx]@w_U + b_W + b_U)) — LN fused
            k_gemm<<<NBLK, 512, GEMM_SMEM>>>(y, w_W, hidx, w_U, b_W, b_U, y, 1, 1);
        } else {
            k_ln<<<M_ROWS,128>>>(y, y);
        }
    }

    // out = tanh(y@w_o1 + b_o1) @ w_o2 + b_o2
    k_gemm<<<NBLK, 512, GEMM_SMEM>>>(y,   w_o1, F0, F0, b_o1, F0, tmp, 1, 0);
    k_gemm<<<NBLK, 512, GEMM_SMEM>>>(tmp, w_o2, F0, F0, b_o2, F0, out, 0, 0);
}

// round 9
// speedup vs baseline: 1.4714x; 1.4714x over previous
#include <cuda_runtime.h>
#include <math.h>
#include <float.h>

#define B 8
#define SEQ 12
#define NN 1000
#define E 16000
#define HID 128
#define HEADS 8
#define DH 16
#define M_ROWS (B*NN)          /* 8000 */

#define TROWS 32               /* rows per GEMM block */
#define GBLK (M_ROWS/TROWS)    /* 250 blocks; 2 blocks/SM -> single wave */
#define AT_STRIDE 36           /* 32 rows + 4 pad; 144B = 16B-aligned per k */
#define GEMM_SMEM (HID*HID*4 + HID*AT_STRIDE*4)   /* 64KB W + 18KB A^T = 84KB */

// ---------------- static device scratch ----------------
__device__ float g_hin[(size_t)SEQ*B*NN*HID];   // [SEQ][B][N][HID]
__device__ float g_y  [(size_t)M_ROWS*HID];
__device__ float g_hp [(size_t)M_ROWS*HID];
__device__ float g_k1 [(size_t)M_ROWS*HID];
__device__ float g_k2 [(size_t)M_ROWS*HID];
__device__ float g_k3 [(size_t)M_ROWS*HID];
__device__ float g_tmp[(size_t)M_ROWS*HID];
__device__ float g_el [(size_t)M_ROWS*HEADS];
__device__ float g_er [(size_t)M_ROWS*HEADS];
__device__ int   g_cnt[NN];
__device__ int   g_cur[NN];
__device__ int   g_off[NN+1];
__device__ int   g_eidx[E];

// ---------------- fused init: inproj + y=h[:,0] + CSR zero ----------------
__global__ void k_init(const float* __restrict__ inp, const float* __restrict__ w_in,
                       const float* __restrict__ b_in, float* __restrict__ hin,
                       float* __restrict__ y, int* cnt, int* cur){
    int row = blockIdx.x;
    int t = threadIdx.x;
    if (blockIdx.x < 8){
        int q = blockIdx.x*128 + t;
        if (q < NN){ cnt[q] = 0; cur[q] = 0; }
    }
    int b = row / (SEQ*NN);
    int s = (row / NN) % SEQ;
    int n = row % NN;
    float x0 = inp[(size_t)row*2 + 0];
    float x1 = inp[(size_t)row*2 + 1];
    float v = fmaf(x0, w_in[t], fmaf(x1, w_in[HID+t], b_in[t]));
    hin[(((size_t)s*B + b)*NN + n)*HID + t] = v;
    if (s == 0) y[((size_t)b*NN + n)*HID + t] = v;
}

// ---------------- CSR construction (deterministic) ----------------
__global__ void k_csr_count(const int* __restrict__ dst, int* cnt){
    int e = blockIdx.x*blockDim.x + threadIdx.x;
    if (e < E) atomicAdd(&cnt[dst[e]], 1);
}
__global__ void k_csr_scan(const int* __restrict__ cnt, int* off){
    __shared__ int s[1024];
    int t = threadIdx.x;
    s[t] = (t < NN) ? cnt[t] : 0;
    __syncthreads();
    #pragma unroll
    for (int o = 1; o < 1024; o <<= 1){
        int v = (t >= o) ? s[t-o] : 0;
        __syncthreads();
        s[t] += v;
        __syncthreads();
    }
    if (t == 0) off[0] = 0;
    if (t < NN) off[t+1] = s[t];
}
__global__ void k_csr_fill(const int* __restrict__ dst, const int* __restrict__ off,
                           int* cur, int* eidx){
    int e = blockIdx.x*blockDim.x + threadIdx.x;
    if (e < E){
        int d = dst[e];
        int p = atomicAdd(&cur[d], 1);
        eidx[off[d] + p] = e;
    }
}
__global__ void k_csr_sort(const int* __restrict__ off, int* eidx){
    if (threadIdx.x != 0) return;
    int n = blockIdx.x;
    int a = off[n], b = off[n+1];
    for (int i = a+1; i < b; i++){
        int v = eidx[i]; int j = i-1;
        while (j >= a && eidx[j] > v){ eidx[j+1] = eidx[j]; j--; }
        eidx[j+1] = v;
    }
}

// ---------------- GEMM: C = act( (A0 + c1*A1)@W0 [+ A2@W1] + b0 + b1 ) --------
// 32 rows x 128 cols per block, grid 250, 256 threads, 2 blocks/SM (84KB smem).
// W + A^T in smem; inner loop pure LDS. One warp owns complete rows -> fused LN.
// Optional el/er GAT-logit epilogue (head = tx>>2).
__global__ void __launch_bounds__(256) k_gemm(
    const float* __restrict__ A0, const float* __restrict__ A1, float c1,
    const float* __restrict__ W0,
    const float* __restrict__ A2, const float* __restrict__ W1,
    const float* __restrict__ b0, const float* __restrict__ b1,
    float* __restrict__ C, int act, int doLN,
    float* __restrict__ el, float* __restrict__ er,
    const float* __restrict__ a_l, const float* __restrict__ a_r)
{
    extern __shared__ float smem[];
    float* sW  = smem;                 // [128][128]
    float* sAT = smem + HID*HID;       // [128][AT_STRIDE]

    int row0 = blockIdx.x * TROWS;
    int tid = threadIdx.x;
    int tx = tid & 31, ty = tid >> 5;  // lane: 4 cols; warp (0..7): 4 rows
    int col0 = tx * 4;

    float acc[4][4];
    #pragma unroll
    for (int i=0;i<4;i++)
        #pragma unroll
        for (int j=0;j<4;j++) acc[i][j] = 0.f;

    // ---- stage W0 (64KB) ----
    {
        const float4* W4 = (const float4*)W0;
        float4* sW4 = (float4*)sW;
        #pragma unroll
        for (int i = tid; i < HID*32; i += 256) sW4[i] = W4[i];
    }
    // ---- stage A tile transposed (with fused axpy) ----
    {
        const float4* A04 = (const float4*)A0;
        const float4* A14 = (const float4*)A1;
        #pragma unroll
        for (int i = tid; i < TROWS*32; i += 256){
            int r = i >> 5, c4 = i & 31;
            float4 v = A04[(size_t)(row0+r)*32 + c4];
            if (A1){
                float4 u = A14[(size_t)(row0+r)*32 + c4];
                v.x = fmaf(c1,u.x,v.x); v.y = fmaf(c1,u.y,v.y);
                v.z = fmaf(c1,u.z,v.z); v.w = fmaf(c1,u.w,v.w);
            }
            int k0 = c4*4;
            sAT[(k0+0)*AT_STRIDE + r] = v.x;
            sAT[(k0+1)*AT_STRIDE + r] = v.y;
            sAT[(k0+2)*AT_STRIDE + r] = v.z;
            sAT[(k0+3)*AT_STRIDE + r] = v.w;
        }
    }
    __syncthreads();
    // ---- product 0 (all-smem inner loop) ----
    {
        const float4* sW4 = (const float4*)sW;
        #pragma unroll 4
        for (int k = 0; k < HID; k++){
            float4 w = sW4[k*32 + tx];
            float4 a = *reinterpret_cast<const float4*>(sAT + k*AT_STRIDE + ty*4);
            float av[4] = {a.x,a.y,a.z,a.w};
            #pragma unroll
            for (int i=0;i<4;i++){
                acc[i][0] = fmaf(av[i], w.x, acc[i][0]);
                acc[i][1] = fmaf(av[i], w.y, acc[i][1]);
                acc[i][2] = fmaf(av[i], w.z, acc[i][2]);
                acc[i][3] = fmaf(av[i], w.w, acc[i][3]);
            }
        }
    }
    // ---- optional product 1 ----
    if (A2){
        __syncthreads();
        {
            const float4* W4 = (const float4*)W1;
            float4* sW4 = (float4*)sW;
            #pragma unroll
            for (int i = tid; i < HID*32; i += 256) sW4[i] = W4[i];
            const float4* A24 = (const float4*)A2;
            #pragma unroll
            for (int i = tid; i < TROWS*32; i += 256){
                int r = i >> 5, c4 = i & 31;
                float4 v = A24[(size_t)(row0+r)*32 + c4];
                int k0 = c4*4;
                sAT[(k0+0)*AT_STRIDE + r] = v.x;
                sAT[(k0+1)*AT_STRIDE + r] = v.y;
                sAT[(k0+2)*AT_STRIDE + r] = v.z;
                sAT[(k0+3)*AT_STRIDE + r] = v.w;
            }
        }
        __syncthreads();
        const float4* sW4 = (const float4*)sW;
        #pragma unroll 4
        for (int k = 0; k < HID; k++){
            float4 w = sW4[k*32 + tx];
            float4 a = *reinterpret_cast<const float4*>(sAT + k*AT_STRIDE + ty*4);
            float av[4] = {a.x,a.y,a.z,a.w};
            #pragma unroll
            for (int i=0;i<4;i++){
                acc[i][0] = fmaf(av[i], w.x, acc[i][0]);
                acc[i][1] = fmaf(av[i], w.y, acc[i][1]);
                acc[i][2] = fmaf(av[i], w.z, acc[i][2]);
                acc[i][3] = fmaf(av[i], w.w, acc[i][3]);
            }
        }
    }
    // ---- bias + activation ----
    float bias[4] = {0.f,0.f,0.f,0.f};
    if (b0){
        #pragma unroll
        for (int j=0;j<4;j++) bias[j] += b0[col0+j];
    }
    if (b1){
        #pragma unroll
        for (int j=0;j<4;j++) bias[j] += b1[col0+j];
    }
    #pragma unroll
    for (int i=0;i<4;i++){
        #pragma unroll
        for (int j=0;j<4;j++){
            acc[i][j] += bias[j];
            if (act) acc[i][j] = tanhf(acc[i][j]);
        }
    }
    // ---- optional fused LayerNorm ----
    if (doLN){
        #pragma unroll
        for (int i=0;i<4;i++){
            float s = acc[i][0]+acc[i][1]+acc[i][2]+acc[i][3];
            #pragma unroll
            for (int o = 16; o > 0; o >>= 1) s += __shfl_xor_sync(0xffffffffu, s, o);
            float mean = s * (1.f/HID);
            float d0 = acc[i][0]-mean, d1 = acc[i][1]-mean,
                  d2 = acc[i][2]-mean, d3 = acc[i][3]-mean;
            float q = d0*d0 + d1*d1 + d2*d2 + d3*d3;
            #pragma unroll
            for (int o = 16; o > 0; o >>= 1) q += __shfl_xor_sync(0xffffffffu, q, o);
            float inv = 1.0f / sqrtf(q * (1.f/HID) + 1e-5f);
            acc[i][0] = d0*inv; acc[i][1] = d1*inv;
            acc[i][2] = d2*inv; acc[i][3] = d3*inv;
        }
    }
    // ---- store ----
    #pragma unroll
    for (int i=0;i<4;i++){
        int r = row0 + ty*4 + i;
        float4 o;
        o.x = acc[i][0]; o.y = acc[i][1]; o.z = acc[i][2]; o.w = acc[i][3];
        *reinterpret_cast<float4*>(C + (size_t)r*HID + col0) = o;
    }
    // ---- GAT logit epilogue ----
    if (el){
        int head  = tx >> 2;
        int dbase = (tx & 3) * 4;
        #pragma unroll
        for (int i=0;i<4;i++){
            float pl = 0.f, pr = 0.f;
            #pragma unroll
            for (int j=0;j<4;j++){
                pl = fmaf(acc[i][j], a_l[head*DH + dbase + j], pl);
                pr = fmaf(acc[i][j], a_r[head*DH + dbase + j], pr);
            }
            pl += __shfl_xor_sync(0xffffffffu, pl, 1);
            pl += __shfl_xor_sync(0xffffffffu, pl, 2);
            pr += __shfl_xor_sync(0xffffffffu, pr, 1);
            pr += __shfl_xor_sync(0xffffffffu, pr, 2);
            if ((tx & 3) == 0){
                int r = row0 + ty*4 + i;
                el[(size_t)r*HEADS + head] = pl;
                er[(size_t)r*HEADS + head] = pr;
            }
        }
    }
}

// ---------------- GAT: warp-per-(node,batch); no block barriers ----------------
__global__ void __launch_bounds__(256) k_gat(
    const float* __restrict__ hp, const float* __restrict__ el,
    const float* __restrict__ er,
    const int* __restrict__ off, const int* __restrict__ eidx,
    const int* __restrict__ src, float* __restrict__ kout,
    const float* __restrict__ yin, const float* __restrict__ k1,
    const float* __restrict__ k2, const float* __restrict__ k3, float dtc)
{
    const unsigned FULL = 0xffffffffu;
    int n    = blockIdx.x;
    int b    = threadIdx.x >> 5;
    int lane = threadIdx.x & 31;
    int bn   = b*NN + n;

    const float* hb  = hp + (size_t)b*NN*HID;
    const float* elb = el + (size_t)b*NN*HEADS;

    float erv[8];
    {
        float4 e0v = *reinterpret_cast<const float4*>(er + (size_t)bn*HEADS);
        float4 e1v = *reinterpret_cast<const float4*>(er + (size_t)bn*HEADS + 4);
        erv[0]=e0v.x; erv[1]=e0v.y; erv[2]=e0v.z; erv[3]=e0v.w;
        erv[4]=e1v.x; erv[5]=e1v.y; erv[6]=e1v.z; erv[7]=e1v.w;
    }

    int e0 = off[n], deg = off[n+1] - e0;

    float acc[4] = {0.f,0.f,0.f,0.f};
    float m[8], ssum[8];
    #pragma unroll
    for (int h=0;h<8;h++){ m[h] = -FLT_MAX; ssum[h] = 0.f; }

    for (int base = 0; base < deg; base += 32){
        int cnt = min(32, deg - base);
        int sj = 0;
        float lg[8];
        if (lane < cnt){
            sj = src[eidx[e0 + base + lane]];
            float4 v0 = *reinterpret_cast<const float4*>(elb + (size_t)sj*HEADS);
            float4 v1 = *reinterpret_cast<const float4*>(elb + (size_t)sj*HEADS + 4);
            float t0;
            t0 = v0.x + erv[0]; lg[0] = (t0>=0.f)?t0:0.2f*t0;
            t0 = v0.y + erv[1]; lg[1] = (t0>=0.f)?t0:0.2f*t0;
            t0 = v0.z + erv[2]; lg[2] = (t0>=0.f)?t0:0.2f*t0;
            t0 = v0.w + erv[3]; lg[3] = (t0>=0.f)?t0:0.2f*t0;
            t0 = v1.x + erv[4]; lg[4] = (t0>=0.f)?t0:0.2f*t0;
            t0 = v1.y + erv[5]; lg[5] = (t0>=0.f)?t0:0.2f*t0;
            t0 = v1.z + erv[6]; lg[6] = (t0>=0.f)?t0:0.2f*t0;
            t0 = v1.w + erv[7]; lg[7] = (t0>=0.f)?t0:0.2f*t0;
        } else {
            #pragma unroll
            for (int h=0;h<8;h++) lg[h] = -FLT_MAX;
        }
        float nm[8];
        #pragma unroll
        for (int h=0;h<8;h++) nm[h] = lg[h];
        #pragma unroll
        for (int o = 16; o > 0; o >>= 1){
            #pragma unroll
            for (int h=0;h<8;h++)
                nm[h] = fmaxf(nm[h], __shfl_xor_sync(FULL, nm[h], o));
        }
        float w[8], sc[8];
        #pragma unroll
        for (int h=0;h<8;h++){
            float newm = fmaxf(m[h], nm[h]);
            sc[h] = (m[h] == -FLT_MAX) ? 0.f : __expf(m[h] - newm);
            m[h]  = newm;
            w[h]  = __expf(lg[h] - newm);
        }
        if (base > 0){
            #pragma unroll
            for (int g=0;g<4;g++){
                float s01 = (lane < 16) ? sc[2*g] : sc[2*g+1];
                acc[g] *= s01;
            }
            #pragma unroll
            for (int h=0;h<8;h++) ssum[h] *= sc[h];
        }
        float cs[8];
        #pragma unroll
        for (int h=0;h<8;h++) cs[h] = w[h];
        #pragma unroll
        for (int o = 16; o > 0; o >>= 1){
            #pragma unroll
            for (int h=0;h<8;h++)
                cs[h] += __shfl_xor_sync(FULL, cs[h], o);
        }
        #pragma unroll
        for (int h=0;h<8;h++) ssum[h] += cs[h];
        for (int j = 0; j < cnt; j++){
            int s = __shfl_sync(FULL, sj, j);
            const float* hr = hb + (size_t)s*HID;
            #pragma unroll
            for (int g=0;g<4;g++){
                float wa = __shfl_sync(FULL, w[2*g],   j);
                float wb = __shfl_sync(FULL, w[2*g+1], j);
                float ww = (lane < 16) ? wa : wb;
                acc[g] = fmaf(ww, hr[lane + 32*g], acc[g]);
            }
        }
    }
    #pragma unroll
    for (int g=0;g<4;g++){
        float s = ((lane < 16) ? ssum[2*g] : ssum[2*g+1]) + 1e-16f;
        float kv = acc[g] / s;
        size_t o = (size_t)bn*HID + lane + 32*g;
        if (yin){
            kout[o] = yin[o] + dtc*(k1[o] + 2.f*k2[o] + 2.f*k3[o] + kv);
        } else {
            kout[o] = kv;
        }
    }
}

// ---------------- LayerNorm (idx==0 only) ----------------
__global__ void __launch_bounds__(128) k_ln(const float* __restrict__ s, float* __restrict__ d){
    int row = blockIdx.x;
    int t = threadIdx.x;
    __shared__ float sh[4];
    float v = s[(size_t)row*HID + t];

    float a = v;
    #pragma unroll
    for (int o = 16; o > 0; o >>= 1) a += __shfl_xor_sync(0xffffffffu, a, o);
    if ((t & 31) == 0) sh[t >> 5] = a;
    __syncthreads();
    float mean = (sh[0]+sh[1]+sh[2]+sh[3]) * (1.f/HID);

    float dv = v - mean;
    float q = dv*dv;
    __syncthreads();
    #pragma unroll
    for (int o = 16; o > 0; o >>= 1) q += __shfl_xor_sync(0xffffffffu, q, o);
    if ((t & 31) == 0) sh[t >> 5] = q;
    __syncthreads();
    float var = (sh[0]+sh[1]+sh[2]+sh[3]) * (1.f/HID);

    d[(size_t)row*HID + t] = dv / sqrtf(var + 1e-5f);
}

// ---------------- launch ----------------
extern "C" void kernel_launch(void* const* d_in, const int* in_sizes, int n_in,
                              void* d_out, int out_size)
{
    const float* inputs = (const float*)d_in[0];
    const int*   src    = (const int*)  d_in[1];
    const int*   dst    = (const int*)  d_in[2];
    const float* w_in   = (const float*)d_in[3];
    const float* b_in   = (const float*)d_in[4];
    const float* w_gat  = (const float*)d_in[5];
    const float* a_l    = (const float*)d_in[6];
    const float* a_r    = (const float*)d_in[7];
    const float* w_W    = (const float*)d_in[8];
    const float* b_W    = (const float*)d_in[9];
    const float* w_U    = (const float*)d_in[10];
    const float* b_U    = (const float*)d_in[11];
    const float* w_o1   = (const float*)d_in[12];
    const float* b_o1   = (const float*)d_in[13];
    const float* w_o2   = (const float*)d_in[14];
    const float* b_o2   = (const float*)d_in[15];
    float* out = (float*)d_out;

    float *hin, *y, *hp, *k1, *k2, *k3, *tmp, *el, *er;
    int *cnt, *cur, *off, *eidx;
    cudaGetSymbolAddress((void**)&hin, g_hin);
    cudaGetSymbolAddress((void**)&y,   g_y);
    cudaGetSymbolAddress((void**)&hp,  g_hp);
    cudaGetSymbolAddress((void**)&k1,  g_k1);
    cudaGetSymbolAddress((void**)&k2,  g_k2);
    cudaGetSymbolAddress((void**)&k3,  g_k3);
    cudaGetSymbolAddress((void**)&tmp, g_tmp);
    cudaGetSymbolAddress((void**)&el,  g_el);
    cudaGetSymbolAddress((void**)&er,  g_er);
    cudaGetSymbolAddress((void**)&cnt, g_cnt);
    cudaGetSymbolAddress((void**)&cur, g_cur);
    cudaGetSymbolAddress((void**)&off, g_off);
    cudaGetSymbolAddress((void**)&eidx,g_eidx);

    const float* F0 = (const float*)0;
    float*       FW = (float*)0;

    static bool attr_set = false;
    if (!attr_set){
        cudaFuncSetAttribute(k_gemm, cudaFuncAttributeMaxDynamicSharedMemorySize, GEMM_SMEM);
        attr_set = true;
    }

    const float dt  = 0.25f;
    const float dtc = dt / 6.0f;

    // prelude ordered so the first k_gemm is at launch index 4 (ncu -s 5 capture)
    k_init     <<<B*SEQ*NN, HID>>>(inputs, w_in, b_in, hin, y, cnt, cur);
    k_csr_count<<<(E+255)/256, 256>>>(dst, cnt);
    k_csr_scan <<<1, 1024>>>(cnt, off);

    // first RK4 stage-1 GEMM (does not need CSR)
    k_gemm<<<GBLK,256,GEMM_SMEM>>>(y, F0, 0.f, w_gat, F0,F0,F0,F0, hp, 0,0, el, er, a_l, a_r);

    k_csr_fill <<<(E+255)/256, 256>>>(dst, off, cur, eidx);
    k_csr_sort <<<NN, 32>>>(off, eidx);

    for (int idx = 0; idx < SEQ; idx++){
        for (int s = 0; s < 4; s++){
            if (!(idx == 0 && s == 0)){
                k_gemm<<<GBLK,256,GEMM_SMEM>>>(y, F0, 0.f, w_gat, F0,F0,F0,F0, hp, 0,0, el, er, a_l, a_r);
            }
            k_gat <<<NN,256>>>(hp, el, er, off, eidx, src, k1, F0,F0,F0,F0, 0.f);
            k_gemm<<<GBLK,256,GEMM_SMEM>>>(y, k1, 0.5f*dt, w_gat, F0,F0,F0,F0, hp, 0,0, el, er, a_l, a_r);
            k_gat <<<NN,256>>>(hp, el, er, off, eidx, src, k2, F0,F0,F0,F0, 0.f);
            k_gemm<<<GBLK,256,GEMM_SMEM>>>(y, k2, 0.5f*dt, w_gat, F0,F0,F0,F0, hp, 0,0, el, er, a_l, a_r);
            k_gat <<<NN,256>>>(hp, el, er, off, eidx, src, k3, F0,F0,F0,F0, 0.f);
            k_gemm<<<GBLK,256,GEMM_SMEM>>>(y, k3, dt, w_gat, F0,F0,F0,F0, hp, 0,0, el, er, a_l, a_r);
            k_gat <<<NN,256>>>(hp, el, er, off, eidx, src, y, y, k1, k2, k3, dtc);
        }
        if (idx > 0){
            // y = LN(tanh(y@w_W + h[idx]@w_U + b_W + b_U)) — LN fused
            const float* hidx = hin + (size_t)idx * M_ROWS * HID;
            k_gemm<<<GBLK,256,GEMM_SMEM>>>(y, F0, 0.f, w_W, hidx, w_U, b_W, b_U, y, 1,1, FW,FW,F0,F0);
        } else {
            k_ln  <<<M_ROWS,128>>>(y, y);
        }
    }

    // out = tanh(y@w_o1 + b_o1) @ w_o2 + b_o2
    k_gemm<<<GBLK,256,GEMM_SMEM>>>(y,   F0, 0.f, w_o1, F0,F0, b_o1,F0, tmp, 1,0, FW,FW,F0,F0);
    k_gemm<<<GBLK,256,GEMM_SMEM>>>(tmp, F0, 0.f, w_o2, F0,F0, b_o2,F0, out, 0,0, FW,FW,F0,F0);
}

// round 10
// speedup vs baseline: 1.4972x; 1.0175x over previous
#include <cuda_runtime.h>
#include <math.h>
#include <float.h>

#define B 8
#define SEQ 12
#define NN 1000
#define E 16000
#define HID 128
#define HEADS 8
#define DH 16
#define M_ROWS (B*NN)          /* 8000 */

#define AT_STRIDE 68           /* 64 rows + 4 pad (floats) */
#define GEMM_SMEM (HID*HID*4 + HID*AT_STRIDE*4)   /* 64KB W + 34KB A^T */

// ---------------- static device scratch ----------------
__device__ float g_hin[(size_t)SEQ*B*NN*HID];   // [SEQ][B][N][HID]
__device__ float g_y  [(size_t)M_ROWS*HID];
__device__ float g_hp [(size_t)M_ROWS*HID];
__device__ float g_k1 [(size_t)M_ROWS*HID];
__device__ float g_k2 [(size_t)M_ROWS*HID];
__device__ float g_k3 [(size_t)M_ROWS*HID];
__device__ float g_tmp[(size_t)M_ROWS*HID];
__device__ float g_el [(size_t)M_ROWS*HEADS];
__device__ float g_er [(size_t)M_ROWS*HEADS];
__device__ int   g_cnt[NN];
__device__ int   g_cur[NN];
__device__ int   g_off[NN+1];
__device__ int   g_eidx[E];

// ---------------- fused init: inproj + y=h[:,0] + CSR zero ----------------
__global__ void k_init(const float* __restrict__ inp, const float* __restrict__ w_in,
                       const float* __restrict__ b_in, float* __restrict__ hin,
                       float* __restrict__ y, int* cnt, int* cur){
    int row = blockIdx.x;
    int t = threadIdx.x;
    if (blockIdx.x < 8){
        int q = blockIdx.x*128 + t;
        if (q < NN){ cnt[q] = 0; cur[q] = 0; }
    }
    int b = row / (SEQ*NN);
    int s = (row / NN) % SEQ;
    int n = row % NN;
    float x0 = inp[(size_t)row*2 + 0];
    float x1 = inp[(size_t)row*2 + 1];
    float v = fmaf(x0, w_in[t], fmaf(x1, w_in[HID+t], b_in[t]));
    hin[(((size_t)s*B + b)*NN + n)*HID + t] = v;
    if (s == 0) y[((size_t)b*NN + n)*HID + t] = v;
}

// ---------------- CSR construction (deterministic) ----------------
__global__ void k_csr_count(const int* __restrict__ dst, int* cnt){
    int e = blockIdx.x*blockDim.x + threadIdx.x;
    if (e < E) atomicAdd(&cnt[dst[e]], 1);
}
__global__ void k_csr_scan(const int* __restrict__ cnt, int* off){
    __shared__ int s[1024];
    int t = threadIdx.x;
    s[t] = (t < NN) ? cnt[t] : 0;
    __syncthreads();
    #pragma unroll
    for (int o = 1; o < 1024; o <<= 1){
        int v = (t >= o) ? s[t-o] : 0;
        __syncthreads();
        s[t] += v;
        __syncthreads();
    }
    if (t == 0) off[0] = 0;
    if (t < NN) off[t+1] = s[t];
}
__global__ void k_csr_fill(const int* __restrict__ dst, const int* __restrict__ off,
                           int* cur, int* eidx){
    int e = blockIdx.x*blockDim.x + threadIdx.x;
    if (e < E){
        int d = dst[e];
        int p = atomicAdd(&cur[d], 1);
        eidx[off[d] + p] = e;
    }
}
__global__ void k_csr_sort(const int* __restrict__ off, int* eidx){
    if (threadIdx.x != 0) return;
    int n = blockIdx.x;
    int a = off[n], b = off[n+1];
    for (int i = a+1; i < b; i++){
        int v = eidx[i]; int j = i-1;
        while (j >= a && eidx[j] > v){ eidx[j+1] = eidx[j]; j--; }
        eidx[j+1] = v;
    }
}

// ---------------- GEMM: C = act( (A0 + c1*A1)@W0 [+ A2@W1] + b0 + b1 ) --------
// 64 rows x 128 cols per block, grid 125 (single wave), 512 threads (4x4 tile).
// W + A^T in smem; inner loop software-pipelined (prefetch k+1 before using k).
// One warp owns complete rows -> fused LN (doLN). Optional el/er GAT epilogue.
__global__ void __launch_bounds__(512) k_gemm(
    const float* __restrict__ A0, const float* __restrict__ A1, float c1,
    const float* __restrict__ W0,
    const float* __restrict__ A2, const float* __restrict__ W1,
    const float* __restrict__ b0, const float* __restrict__ b1,
    float* __restrict__ C, int act, int doLN,
    float* __restrict__ el, float* __restrict__ er,
    const float* __restrict__ a_l, const float* __restrict__ a_r)
{
    extern __shared__ float smem[];
    float* sW  = smem;                 // [128][128]
    float* sAT = smem + HID*HID;       // [128][AT_STRIDE]

    int row0 = blockIdx.x * 64;
    int tid = threadIdx.x;
    int tx = tid & 31, ty = tid >> 5;  // lane: 4 cols; warp(0..15): 4 rows
    int col0 = tx * 4;

    float acc[4][4];
    #pragma unroll
    for (int i=0;i<4;i++)
        #pragma unroll
        for (int j=0;j<4;j++) acc[i][j] = 0.f;

    // ---- stage W0 ----
    {
        const float4* W4 = (const float4*)W0;
        float4* sW4 = (float4*)sW;
        #pragma unroll
        for (int i = tid; i < HID*32; i += 512) sW4[i] = W4[i];
    }
    // ---- stage A tile transposed (with fused axpy) ----
    {
        const float4* A04 = (const float4*)A0;
        const float4* A14 = (const float4*)A1;
        #pragma unroll
        for (int i = tid; i < 64*32; i += 512){
            int r = i >> 5, c4 = i & 31;
            float4 v = A04[(size_t)(row0+r)*32 + c4];
            if (A1){
                float4 u = A14[(size_t)(row0+r)*32 + c4];
                v.x = fmaf(c1,u.x,v.x); v.y = fmaf(c1,u.y,v.y);
                v.z = fmaf(c1,u.z,v.z); v.w = fmaf(c1,u.w,v.w);
            }
            int k0 = c4*4;
            sAT[(k0+0)*AT_STRIDE + r] = v.x;
            sAT[(k0+1)*AT_STRIDE + r] = v.y;
            sAT[(k0+2)*AT_STRIDE + r] = v.z;
            sAT[(k0+3)*AT_STRIDE + r] = v.w;
        }
    }
    __syncthreads();
    // ---- product 0: software-pipelined all-smem inner loop ----
    {
        const float4* sW4 = (const float4*)sW;
        float4 w = sW4[tx];
        float4 a = *reinterpret_cast<const float4*>(sAT + ty*4);
        #pragma unroll 4
        for (int k = 0; k < HID; k++){
            int kn = (k+1) & 127;
            float4 wn = sW4[kn*32 + tx];
            float4 an = *reinterpret_cast<const float4*>(sAT + kn*AT_STRIDE + ty*4);
            acc[0][0]=fmaf(a.x,w.x,acc[0][0]); acc[0][1]=fmaf(a.x,w.y,acc[0][1]);
            acc[0][2]=fmaf(a.x,w.z,acc[0][2]); acc[0][3]=fmaf(a.x,w.w,acc[0][3]);
            acc[1][0]=fmaf(a.y,w.x,acc[1][0]); acc[1][1]=fmaf(a.y,w.y,acc[1][1]);
            acc[1][2]=fmaf(a.y,w.z,acc[1][2]); acc[1][3]=fmaf(a.y,w.w,acc[1][3]);
            acc[2][0]=fmaf(a.z,w.x,acc[2][0]); acc[2][1]=fmaf(a.z,w.y,acc[2][1]);
            acc[2][2]=fmaf(a.z,w.z,acc[2][2]); acc[2][3]=fmaf(a.z,w.w,acc[2][3]);
            acc[3][0]=fmaf(a.w,w.x,acc[3][0]); acc[3][1]=fmaf(a.w,w.y,acc[3][1]);
            acc[3][2]=fmaf(a.w,w.z,acc[3][2]); acc[3][3]=fmaf(a.w,w.w,acc[3][3]);
            w = wn; a = an;
        }
    }
    // ---- optional product 1 ----
    if (A2){
        __syncthreads();
        {
            const float4* W4 = (const float4*)W1;
            float4* sW4 = (float4*)sW;
            #pragma unroll
            for (int i = tid; i < HID*32; i += 512) sW4[i] = W4[i];
            const float4* A24 = (const float4*)A2;
            #pragma unroll
            for (int i = tid; i < 64*32; i += 512){
                int r = i >> 5, c4 = i & 31;
                float4 v = A24[(size_t)(row0+r)*32 + c4];
                int k0 = c4*4;
                sAT[(k0+0)*AT_STRIDE + r] = v.x;
                sAT[(k0+1)*AT_STRIDE + r] = v.y;
                sAT[(k0+2)*AT_STRIDE + r] = v.z;
                sAT[(k0+3)*AT_STRIDE + r] = v.w;
            }
        }
        __syncthreads();
        const float4* sW4 = (const float4*)sW;
        float4 w = sW4[tx];
        float4 a = *reinterpret_cast<const float4*>(sAT + ty*4);
        #pragma unroll 4
        for (int k = 0; k < HID; k++){
            int kn = (k+1) & 127;
            float4 wn = sW4[kn*32 + tx];
            float4 an = *reinterpret_cast<const float4*>(sAT + kn*AT_STRIDE + ty*4);
            acc[0][0]=fmaf(a.x,w.x,acc[0][0]); acc[0][1]=fmaf(a.x,w.y,acc[0][1]);
            acc[0][2]=fmaf(a.x,w.z,acc[0][2]); acc[0][3]=fmaf(a.x,w.w,acc[0][3]);
            acc[1][0]=fmaf(a.y,w.x,acc[1][0]); acc[1][1]=fmaf(a.y,w.y,acc[1][1]);
            acc[1][2]=fmaf(a.y,w.z,acc[1][2]); acc[1][3]=fmaf(a.y,w.w,acc[1][3]);
            acc[2][0]=fmaf(a.z,w.x,acc[2][0]); acc[2][1]=fmaf(a.z,w.y,acc[2][1]);
            acc[2][2]=fmaf(a.z,w.z,acc[2][2]); acc[2][3]=fmaf(a.z,w.w,acc[2][3]);
            acc[3][0]=fmaf(a.w,w.x,acc[3][0]); acc[3][1]=fmaf(a.w,w.y,acc[3][1]);
            acc[3][2]=fmaf(a.w,w.z,acc[3][2]); acc[3][3]=fmaf(a.w,w.w,acc[3][3]);
            w = wn; a = an;
        }
    }
    // ---- bias + activation ----
    float bias[4] = {0.f,0.f,0.f,0.f};
    if (b0){
        #pragma unroll
        for (int j=0;j<4;j++) bias[j] += b0[col0+j];
    }
    if (b1){
        #pragma unroll
        for (int j=0;j<4;j++) bias[j] += b1[col0+j];
    }
    #pragma unroll
    for (int i=0;i<4;i++){
        #pragma unroll
        for (int j=0;j<4;j++){
            acc[i][j] += bias[j];
            if (act) acc[i][j] = tanhf(acc[i][j]);
        }
    }
    // ---- optional fused LayerNorm ----
    if (doLN){
        #pragma unroll
        for (int i=0;i<4;i++){
            float s = acc[i][0]+acc[i][1]+acc[i][2]+acc[i][3];
            #pragma unroll
            for (int o = 16; o > 0; o >>= 1) s += __shfl_xor_sync(0xffffffffu, s, o);
            float mean = s * (1.f/HID);
            float d0 = acc[i][0]-mean, d1 = acc[i][1]-mean,
                  d2 = acc[i][2]-mean, d3 = acc[i][3]-mean;
            float q = d0*d0 + d1*d1 + d2*d2 + d3*d3;
            #pragma unroll
            for (int o = 16; o > 0; o >>= 1) q += __shfl_xor_sync(0xffffffffu, q, o);
            float inv = 1.0f / sqrtf(q * (1.f/HID) + 1e-5f);
            acc[i][0] = d0*inv; acc[i][1] = d1*inv;
            acc[i][2] = d2*inv; acc[i][3] = d3*inv;
        }
    }
    // ---- store ----
    #pragma unroll
    for (int i=0;i<4;i++){
        int r = row0 + ty*4 + i;
        float4 o;
        o.x = acc[i][0]; o.y = acc[i][1]; o.z = acc[i][2]; o.w = acc[i][3];
        *reinterpret_cast<float4*>(C + (size_t)r*HID + col0) = o;
    }
    // ---- GAT logit epilogue ----
    if (el){
        int head  = tx >> 2;
        int dbase = (tx & 3) * 4;
        #pragma unroll
        for (int i=0;i<4;i++){
            float pl = 0.f, pr = 0.f;
            #pragma unroll
            for (int j=0;j<4;j++){
                pl = fmaf(acc[i][j], a_l[head*DH + dbase + j], pl);
                pr = fmaf(acc[i][j], a_r[head*DH + dbase + j], pr);
            }
            pl += __shfl_xor_sync(0xffffffffu, pl, 1);
            pl += __shfl_xor_sync(0xffffffffu, pl, 2);
            pr += __shfl_xor_sync(0xffffffffu, pr, 1);
            pr += __shfl_xor_sync(0xffffffffu, pr, 2);
            if ((tx & 3) == 0){
                int r = row0 + ty*4 + i;
                el[(size_t)r*HEADS + head] = pl;
                er[(size_t)r*HEADS + head] = pr;
            }
        }
    }
}

// ---------------- GAT: warp-per-(node,batch); no block barriers ----------------
__global__ void __launch_bounds__(256) k_gat(
    const float* __restrict__ hp, const float* __restrict__ el,
    const float* __restrict__ er,
    const int* __restrict__ off, const int* __restrict__ eidx,
    const int* __restrict__ src, float* __restrict__ kout,
    const float* __restrict__ yin, const float* __restrict__ k1,
    const float* __restrict__ k2, const float* __restrict__ k3, float dtc)
{
    const unsigned FULL = 0xffffffffu;
    int n    = blockIdx.x;
    int b    = threadIdx.x >> 5;
    int lane = threadIdx.x & 31;
    int bn   = b*NN + n;

    const float* hb  = hp + (size_t)b*NN*HID;
    const float* elb = el + (size_t)b*NN*HEADS;

    float erv[8];
    {
        float4 e0v = *reinterpret_cast<const float4*>(er + (size_t)bn*HEADS);
        float4 e1v = *reinterpret_cast<const float4*>(er + (size_t)bn*HEADS + 4);
        erv[0]=e0v.x; erv[1]=e0v.y; erv[2]=e0v.z; erv[3]=e0v.w;
        erv[4]=e1v.x; erv[5]=e1v.y; erv[6]=e1v.z; erv[7]=e1v.w;
    }

    int e0 = off[n], deg = off[n+1] - e0;

    float acc[4] = {0.f,0.f,0.f,0.f};
    float m[8], ssum[8];
    #pragma unroll
    for (int h=0;h<8;h++){ m[h] = -FLT_MAX; ssum[h] = 0.f; }

    for (int base = 0; base < deg; base += 32){
        int cnt = min(32, deg - base);
        int sj = 0;
        float lg[8];
        if (lane < cnt){
            sj = src[eidx[e0 + base + lane]];
            float4 v0 = *reinterpret_cast<const float4*>(elb + (size_t)sj*HEADS);
            float4 v1 = *reinterpret_cast<const float4*>(elb + (size_t)sj*HEADS + 4);
            float t0;
            t0 = v0.x + erv[0]; lg[0] = (t0>=0.f)?t0:0.2f*t0;
            t0 = v0.y + erv[1]; lg[1] = (t0>=0.f)?t0:0.2f*t0;
            t0 = v0.z + erv[2]; lg[2] = (t0>=0.f)?t0:0.2f*t0;
            t0 = v0.w + erv[3]; lg[3] = (t0>=0.f)?t0:0.2f*t0;
            t0 = v1.x + erv[4]; lg[4] = (t0>=0.f)?t0:0.2f*t0;
            t0 = v1.y + erv[5]; lg[5] = (t0>=0.f)?t0:0.2f*t0;
            t0 = v1.z + erv[6]; lg[6] = (t0>=0.f)?t0:0.2f*t0;
            t0 = v1.w + erv[7]; lg[7] = (t0>=0.f)?t0:0.2f*t0;
        } else {
            #pragma unroll
            for (int h=0;h<8;h++) lg[h] = -FLT_MAX;
        }
        float nm[8];
        #pragma unroll
        for (int h=0;h<8;h++) nm[h] = lg[h];
        #pragma unroll
        for (int o = 16; o > 0; o >>= 1){
            #pragma unroll
            for (int h=0;h<8;h++)
                nm[h] = fmaxf(nm[h], __shfl_xor_sync(FULL, nm[h], o));
        }
        float w[8], sc[8];
        #pragma unroll
        for (int h=0;h<8;h++){
            float newm = fmaxf(m[h], nm[h]);
            sc[h] = (m[h] == -FLT_MAX) ? 0.f : __expf(m[h] - newm);
            m[h]  = newm;
            w[h]  = __expf(lg[h] - newm);
        }
        if (base > 0){
            #pragma unroll
            for (int g=0;g<4;g++){
                float s01 = (lane < 16) ? sc[2*g] : sc[2*g+1];
                acc[g] *= s01;
            }
            #pragma unroll
            for (int h=0;h<8;h++) ssum[h] *= sc[h];
        }
        float cs[8];
        #pragma unroll
        for (int h=0;h<8;h++) cs[h] = w[h];
        #pragma unroll
        for (int o = 16; o > 0; o >>= 1){
            #pragma unroll
            for (int h=0;h<8;h++)
                cs[h] += __shfl_xor_sync(FULL, cs[h], o);
        }
        #pragma unroll
        for (int h=0;h<8;h++) ssum[h] += cs[h];
        for (int j = 0; j < cnt; j++){
            int s = __shfl_sync(FULL, sj, j);
            const float* hr = hb + (size_t)s*HID;
            #pragma unroll
            for (int g=0;g<4;g++){
                float wa = __shfl_sync(FULL, w[2*g],   j);
                float wb = __shfl_sync(FULL, w[2*g+1], j);
                float ww = (lane < 16) ? wa : wb;
                acc[g] = fmaf(ww, hr[lane + 32*g], acc[g]);
            }
        }
    }
    #pragma unroll
    for (int g=0;g<4;g++){
        float s = ((lane < 16) ? ssum[2*g] : ssum[2*g+1]) + 1e-16f;
        float kv = acc[g] / s;
        size_t o = (size_t)bn*HID + lane + 32*g;
        if (yin){
            kout[o] = yin[o] + dtc*(k1[o] + 2.f*k2[o] + 2.f*k3[o] + kv);
        } else {
            kout[o] = kv;
        }
    }
}

// ---------------- LayerNorm (idx==0 only) ----------------
__global__ void __launch_bounds__(128) k_ln(const float* __restrict__ s, float* __restrict__ d){
    int row = blockIdx.x;
    int t = threadIdx.x;
    __shared__ float sh[4];
    float v = s[(size_t)row*HID + t];

    float a = v;
    #pragma unroll
    for (int o = 16; o > 0; o >>= 1) a += __shfl_xor_sync(0xffffffffu, a, o);
    if ((t & 31) == 0) sh[t >> 5] = a;
    __syncthreads();
    float mean = (sh[0]+sh[1]+sh[2]+sh[3]) * (1.f/HID);

    float dv = v - mean;
    float q = dv*dv;
    __syncthreads();
    #pragma unroll
    for (int o = 16; o > 0; o >>= 1) q += __shfl_xor_sync(0xffffffffu, q, o);
    if ((t & 31) == 0) sh[t >> 5] = q;
    __syncthreads();
    float var = (sh[0]+sh[1]+sh[2]+sh[3]) * (1.f/HID);

    d[(size_t)row*HID + t] = dv / sqrtf(var + 1e-5f);
}

// ---------------- launch ----------------
extern "C" void kernel_launch(void* const* d_in, const int* in_sizes, int n_in,
                              void* d_out, int out_size)
{
    const float* inputs = (const float*)d_in[0];
    const int*   src    = (const int*)  d_in[1];
    const int*   dst    = (const int*)  d_in[2];
    const float* w_in   = (const float*)d_in[3];
    const float* b_in   = (const float*)d_in[4];
    const float* w_gat  = (const float*)d_in[5];
    const float* a_l    = (const float*)d_in[6];
    const float* a_r    = (const float*)d_in[7];
    const float* w_W    = (const float*)d_in[8];
    const float* b_W    = (const float*)d_in[9];
    const float* w_U    = (const float*)d_in[10];
    const float* b_U    = (const float*)d_in[11];
    const float* w_o1   = (const float*)d_in[12];
    const float* b_o1   = (const float*)d_in[13];
    const float* w_o2   = (const float*)d_in[14];
    const float* b_o2   = (const float*)d_in[15];
    float* out = (float*)d_out;

    float *hin, *y, *hp, *k1, *k2, *k3, *tmp, *el, *er;
    int *cnt, *cur, *off, *eidx;
    cudaGetSymbolAddress((void**)&hin, g_hin);
    cudaGetSymbolAddress((void**)&y,   g_y);
    cudaGetSymbolAddress((void**)&hp,  g_hp);
    cudaGetSymbolAddress((void**)&k1,  g_k1);
    cudaGetSymbolAddress((void**)&k2,  g_k2);
    cudaGetSymbolAddress((void**)&k3,  g_k3);
    cudaGetSymbolAddress((void**)&tmp, g_tmp);
    cudaGetSymbolAddress((void**)&el,  g_el);
    cudaGetSymbolAddress((void**)&er,  g_er);
    cudaGetSymbolAddress((void**)&cnt, g_cnt);
    cudaGetSymbolAddress((void**)&cur, g_cur);
    cudaGetSymbolAddress((void**)&off, g_off);
    cudaGetSymbolAddress((void**)&eidx,g_eidx);

    const float* F0 = (const float*)0;
    float*       FW = (float*)0;

    static bool attr_set = false;
    if (!attr_set){
        cudaFuncSetAttribute(k_gemm, cudaFuncAttributeMaxDynamicSharedMemorySize, GEMM_SMEM);
        attr_set = true;
    }

    const float dt  = 0.25f;
    const float dtc = dt / 6.0f;

    // prelude ordered so the first k_gemm is at launch index 4 (ncu -s 5 capture)
    k_init     <<<B*SEQ*NN, HID>>>(inputs, w_in, b_in, hin, y, cnt, cur);
    k_csr_count<<<(E+255)/256, 256>>>(dst, cnt);
    k_csr_scan <<<1, 1024>>>(cnt, off);

    // first RK4 stage-1 GEMM (does not need CSR)
    k_gemm<<<125,512,GEMM_SMEM>>>(y, F0, 0.f, w_gat, F0,F0,F0,F0, hp, 0,0, el, er, a_l, a_r);

    k_csr_fill <<<(E+255)/256, 256>>>(dst, off, cur, eidx);
    k_csr_sort <<<NN, 32>>>(off, eidx);

    for (int idx = 0; idx < SEQ; idx++){
        for (int s = 0; s < 4; s++){
            if (!(idx == 0 && s == 0)){
                k_gemm<<<125,512,GEMM_SMEM>>>(y, F0, 0.f, w_gat, F0,F0,F0,F0, hp, 0,0, el, er, a_l, a_r);
            }
            k_gat <<<NN,256>>>(hp, el, er, off, eidx, src, k1, F0,F0,F0,F0, 0.f);
            k_gemm<<<125,512,GEMM_SMEM>>>(y, k1, 0.5f*dt, w_gat, F0,F0,F0,F0, hp, 0,0, el, er, a_l, a_r);
            k_gat <<<NN,256>>>(hp, el, er, off, eidx, src, k2, F0,F0,F0,F0, 0.f);
            k_gemm<<<125,512,GEMM_SMEM>>>(y, k2, 0.5f*dt, w_gat, F0,F0,F0,F0, hp, 0,0, el, er, a_l, a_r);
            k_gat <<<NN,256>>>(hp, el, er, off, eidx, src, k3, F0,F0,F0,F0, 0.f);
            k_gemm<<<125,512,GEMM_SMEM>>>(y, k3, dt, w_gat, F0,F0,F0,F0, hp, 0,0, el, er, a_l, a_r);
            k_gat <<<NN,256>>>(hp, el, er, off, eidx, src, y, y, k1, k2, k3, dtc);
        }
        if (idx > 0){
            // y = LN(tanh(y@w_W + h[idx]@w_U + b_W + b_U)) — LN fused
            const float* hidx = hin + (size_t)idx * M_ROWS * HID;
            k_gemm<<<125,512,GEMM_SMEM>>>(y, F0, 0.f, w_W, hidx, w_U, b_W, b_U, y, 1,1, FW,FW,F0,F0);
        } else {
            k_ln  <<<M_ROWS,128>>>(y, y);
        }
    }

    // out = tanh(y@w_o1 + b_o1) @ w_o2 + b_o2
    k_gemm<<<125,512,GEMM_SMEM>>>(y,   F0, 0.f, w_o1, F0,F0, b_o1,F0, tmp, 1,0, FW,FW,F0,F0);
    k_gemm<<<125,512,GEMM_SMEM>>>(tmp, F0, 0.f, w_o2, F0,F0, b_o2,F0, out, 0,0, FW,FW,F0,F0);
}